// round 4
// baseline (speedup 1.0000x reference)
#include <cuda_runtime.h>
#include <cuda_fp16.h>
#include <math.h>
#include <stdint.h>

#define BB 128
#define HH 512
#define SS 2048

// Scratch (device globals: no allocations allowed)
__device__ float g_u_part[4][BB][SS];
__device__ float g_attn[BB][SS];
__device__ float g_context[BB][HH];
__device__ float g_h1[BB][HH];
__device__ float g_mlp_out[BB][HH];

__device__ __forceinline__ uint32_t smem_u32(const void* p) {
    uint32_t a;
    asm("{ .reg .u64 t; cvta.to.shared.u64 t, %1; cvt.u32.u64 %0, t; }" : "=r"(a) : "l"(p));
    return a;
}
__device__ __forceinline__ float tanh_fast(float x) {
    float y; asm("tanh.approx.f32 %0, %1;" : "=f"(y) : "f"(x)); return y;
}
__device__ __forceinline__ unsigned f2h2(float a, float b) {
    __half2 h = __floats2half2_rn(a, b);
    return *reinterpret_cast<unsigned*>(&h);
}

#define LDSM_X4(r0, r1, r2, r3, addr) \
    asm volatile("ldmatrix.sync.aligned.m8n8.x4.shared.b16 {%0,%1,%2,%3}, [%4];" \
        : "=r"(r0), "=r"(r1), "=r"(r2), "=r"(r3) : "r"(addr))
#define LDSM_X4_T(r0, r1, r2, r3, addr) \
    asm volatile("ldmatrix.sync.aligned.m8n8.x4.trans.shared.b16 {%0,%1,%2,%3}, [%4];" \
        : "=r"(r0), "=r"(r1), "=r"(r2), "=r"(r3) : "r"(addr))
#define MMA16816(c, a, b) \
    asm volatile("mma.sync.aligned.m16n8k16.row.col.f32.f16.f16.f32 " \
        "{%0,%1,%2,%3}, {%4,%5,%6,%7}, {%8,%9}, {%0,%1,%2,%3};" \
        : "+f"((c)[0]), "+f"((c)[1]), "+f"((c)[2]), "+f"((c)[3]) \
        : "r"((a)[0]), "r"((a)[1]), "r"((a)[2]), "r"((a)[3]), \
          "r"((b)[0]), "r"((b)[1]))

// ---------------------------------------------------------------------------
// Kernel 1: scores+u via fp16 mma.sync (m16n8k16), tile 128(h) x 128(s), K=32
// chunks, double-buffered smem, fp32->fp16 conversion in registers.
// grid (S/128, H/128, B) = (16, 4, 128), 256 threads (2x4 warps).
// A (W) smem: 128 rows x 80B (64B data + 16B pad). B (ah, [k][s]): 32 x 272B.
// ---------------------------------------------------------------------------
#define ASTRIDE 80
#define BSTRIDE 272
#define ABUF (128 * ASTRIDE)   // 10240
#define BBUF (32 * BSTRIDE)    // 8704
#define NCHUNK 16

__global__ __launch_bounds__(256, 1) void scores_u_kernel(
    const float* __restrict__ ah, const float* __restrict__ W,
    const float* __restrict__ v_att)
{
    __shared__ char sA[2 * ABUF];
    __shared__ char sB[2 * BBUF];
    __shared__ float su[128];

    const int tid = threadIdx.x;
    const int wid = tid >> 5;
    const int lane = tid & 31;
    const int g = lane >> 2;
    const int t = lane & 3;
    const int warp_m = wid & 1;
    const int warp_n = wid >> 1;
    const int s0 = blockIdx.x * 128;
    const int h0 = blockIdx.y * 128;
    const int b = blockIdx.z;

    const float* ahb = ah + (size_t)b * ((size_t)HH * SS);
    const uint32_t sAb = smem_u32(sA);
    const uint32_t sBb = smem_u32(sB);

    // Per-lane ldmatrix address offsets
    const int lr = lane & 7, sel = lane >> 3;
    const uint32_t a_off = (uint32_t)((warp_m * 64 + (sel & 1) * 8 + lr) * ASTRIDE
                                      + (sel >> 1) * 16);
    const uint32_t b_off = (uint32_t)(((sel & 1) * 8 + lr) * BSTRIDE
                                      + (warp_n * 32 + (sel >> 1) * 8) * 2);

    float acc[4][4][4];
    #pragma unroll
    for (int i = 0; i < 4; i++)
        #pragma unroll
        for (int j = 0; j < 4; j++)
            #pragma unroll
            for (int k = 0; k < 4; k++) acc[i][j][k] = 0.f;
    if (tid < 128) su[tid] = 0.f;

    float4 pa[4], pb[4];
    // Load chunk 0
    #pragma unroll
    for (int f = 0; f < 4; f++) {
        int idx = tid + f * 256;
        int r = idx >> 3, q = idx & 7;
        pa[f] = *(const float4*)&W[(size_t)(h0 + r) * HH + q * 4];
        int kk = idx >> 5, q2 = idx & 31;
        pb[f] = *(const float4*)&ahb[(size_t)kk * SS + s0 + q2 * 4];
    }
    // STS chunk 0 -> buffer 0
    #pragma unroll
    for (int f = 0; f < 4; f++) {
        int idx = tid + f * 256;
        int r = idx >> 3, q = idx & 7;
        *(uint2*)(sA + r * ASTRIDE + q * 8) =
            make_uint2(f2h2(pa[f].x, pa[f].y), f2h2(pa[f].z, pa[f].w));
        int kk = idx >> 5, q2 = idx & 31;
        *(uint2*)(sB + kk * BSTRIDE + q2 * 8) =
            make_uint2(f2h2(pb[f].x, pb[f].y), f2h2(pb[f].z, pb[f].w));
    }
    __syncthreads();

    for (int i = 0; i < NCHUNK; i++) {
        // Prefetch chunk i+1 into registers (overlaps with MMA below)
        if (i + 1 < NCHUNK) {
            int k0 = (i + 1) * 32;
            #pragma unroll
            for (int f = 0; f < 4; f++) {
                int idx = tid + f * 256;
                int r = idx >> 3, q = idx & 7;
                pa[f] = *(const float4*)&W[(size_t)(h0 + r) * HH + k0 + q * 4];
                int kk = idx >> 5, q2 = idx & 31;
                pb[f] = *(const float4*)&ahb[(size_t)(k0 + kk) * SS + s0 + q2 * 4];
            }
        }
        // Compute chunk i from buffer (i & 1)
        {
            const int slot = i & 1;
            const uint32_t abase = sAb + slot * ABUF + a_off;
            const uint32_t bbase = sBb + slot * BBUF + b_off;
            #pragma unroll
            for (int kk = 0; kk < 2; kk++) {
                uint32_t afr[4][4];
                #pragma unroll
                for (int ma = 0; ma < 4; ma++)
                    LDSM_X4(afr[ma][0], afr[ma][1], afr[ma][2], afr[ma][3],
                            abase + kk * 32 + ma * (16 * ASTRIDE));
                uint32_t bfr[4][2];
                #pragma unroll
                for (int nb = 0; nb < 2; nb++)
                    LDSM_X4_T(bfr[2 * nb][0], bfr[2 * nb][1],
                              bfr[2 * nb + 1][0], bfr[2 * nb + 1][1],
                              bbase + kk * (16 * BSTRIDE) + nb * 32);
                #pragma unroll
                for (int ma = 0; ma < 4; ma++)
                    #pragma unroll
                    for (int na = 0; na < 4; na++)
                        MMA16816(acc[ma][na], afr[ma], bfr[na]);
            }
        }
        if (i + 1 < NCHUNK) {
            __syncthreads();
            const int nslot = (i + 1) & 1;
            #pragma unroll
            for (int f = 0; f < 4; f++) {
                int idx = tid + f * 256;
                int r = idx >> 3, q = idx & 7;
                *(uint2*)(sA + nslot * ABUF + r * ASTRIDE + q * 8) =
                    make_uint2(f2h2(pa[f].x, pa[f].y), f2h2(pa[f].z, pa[f].w));
                int kk = idx >> 5, q2 = idx & 31;
                *(uint2*)(sB + nslot * BBUF + kk * BSTRIDE + q2 * 8) =
                    make_uint2(f2h2(pb[f].x, pb[f].y), f2h2(pb[f].z, pb[f].w));
            }
            __syncthreads();
        }
    }

    // Epilogue: u[s-tile] partial = sum_h v_att[h]*tanh(score[h][s])
    // C frag layout: c0:(g,2t) c1:(g,2t+1) c2:(g+8,2t) c3:(g+8,2t+1)
    float vr[4][2];
    #pragma unroll
    for (int ma = 0; ma < 4; ma++) {
        int r = h0 + warp_m * 64 + ma * 16 + g;
        vr[ma][0] = __ldg(&v_att[r]);
        vr[ma][1] = __ldg(&v_att[r + 8]);
    }
    float ucol[8];
    #pragma unroll
    for (int i = 0; i < 8; i++) ucol[i] = 0.f;
    #pragma unroll
    for (int ma = 0; ma < 4; ma++)
        #pragma unroll
        for (int na = 0; na < 4; na++) {
            ucol[na * 2 + 0] += vr[ma][0] * tanh_fast(acc[ma][na][0])
                              + vr[ma][1] * tanh_fast(acc[ma][na][2]);
            ucol[na * 2 + 1] += vr[ma][0] * tanh_fast(acc[ma][na][1])
                              + vr[ma][1] * tanh_fast(acc[ma][na][3]);
        }
    __syncthreads();
    #pragma unroll
    for (int na = 0; na < 4; na++) {
        atomicAdd(&su[warp_n * 32 + na * 8 + 2 * t + 0], ucol[na * 2 + 0]);
        atomicAdd(&su[warp_n * 32 + na * 8 + 2 * t + 1], ucol[na * 2 + 1]);
    }
    __syncthreads();
    if (tid < 128) g_u_part[blockIdx.y][b][s0 + tid] = su[tid];
}

// ---------------------------------------------------------------------------
// Kernel 2: softmax over s per batch
// ---------------------------------------------------------------------------
__global__ __launch_bounds__(256) void softmax_kernel() {
    const int b = blockIdx.x, tid = threadIdx.x;
    __shared__ float red[8];
    __shared__ float bcast;
    float v[8];
    #pragma unroll
    for (int i = 0; i < 8; i++) {
        int s = tid + i * 256;
        v[i] = g_u_part[0][b][s] + g_u_part[1][b][s]
             + g_u_part[2][b][s] + g_u_part[3][b][s];
    }
    float m = -INFINITY;
    #pragma unroll
    for (int i = 0; i < 8; i++) m = fmaxf(m, v[i]);
    #pragma unroll
    for (int o = 16; o; o >>= 1) m = fmaxf(m, __shfl_xor_sync(0xffffffffu, m, o));
    if ((tid & 31) == 0) red[tid >> 5] = m;
    __syncthreads();
    if (tid == 0) {
        float x = red[0];
        #pragma unroll
        for (int i = 1; i < 8; i++) x = fmaxf(x, red[i]);
        bcast = x;
    }
    __syncthreads();
    m = bcast;
    float sum = 0.f;
    #pragma unroll
    for (int i = 0; i < 8; i++) { v[i] = expf(v[i] - m); sum += v[i]; }
    #pragma unroll
    for (int o = 16; o; o >>= 1) sum += __shfl_xor_sync(0xffffffffu, sum, o);
    __syncthreads();
    if ((tid & 31) == 0) red[tid >> 5] = sum;
    __syncthreads();
    if (tid == 0) {
        float x = 0.f;
        #pragma unroll
        for (int i = 0; i < 8; i++) x += red[i];
        bcast = x;
    }
    __syncthreads();
    float inv = 1.f / bcast;
    #pragma unroll
    for (int i = 0; i < 8; i++) g_attn[b][tid + i * 256] = v[i] * inv;
}

// ---------------------------------------------------------------------------
// Kernel 3: context[b][h] = sum_s attn[b][s]*ah[b][h][s], warp per row
// ---------------------------------------------------------------------------
__global__ __launch_bounds__(256) void context_kernel(const float* __restrict__ ah) {
    int gw = blockIdx.x * 8 + (threadIdx.x >> 5);
    int lane = threadIdx.x & 31;
    int b = gw >> 9, h = gw & 511;
    const float4* a4 = reinterpret_cast<const float4*>(&ah[((size_t)b * HH + h) * SS]);
    const float4* t4 = reinterpret_cast<const float4*>(&g_attn[b][0]);
    float acc = 0.f;
    #pragma unroll
    for (int it = 0; it < 16; it++) {
        float4 x = a4[it * 32 + lane];
        float4 w = t4[it * 32 + lane];
        acc += x.x * w.x + x.y * w.y + x.z * w.z + x.w * w.w;
    }
    #pragma unroll
    for (int o = 16; o; o >>= 1) acc += __shfl_xor_sync(0xffffffffu, acc, o);
    if (lane == 0) g_context[b][h] = acc;
}

// ---------------------------------------------------------------------------
// Kernel 4: out[b][j] = relu(in[b] . w[j] + bias[j])
// grid (8 j-tiles of 64, 16 b-tiles of 8), 256 thr: (j, 2 b) per thread
// ---------------------------------------------------------------------------
__global__ __launch_bounds__(256) void linear_relu_kernel(
    int phase, const float* __restrict__ w, const float* __restrict__ bias)
{
    __shared__ float s_in[8][512];
    const int jt = blockIdx.x, bt = blockIdx.y;
    const float* in = phase ? &g_h1[0][0] : &g_context[0][0];
    float* out      = phase ? &g_mlp_out[0][0] : &g_h1[0][0];
    for (int t = threadIdx.x; t < 8 * 128; t += 256) {
        int bb = t >> 7, q = t & 127;
        ((float4*)&s_in[bb][0])[q] = ((const float4*)&in[(size_t)(bt * 8 + bb) * 512])[q];
    }
    __syncthreads();
    const int j = jt * 64 + (threadIdx.x & 63);
    const int bp = threadIdx.x >> 6;
    const int b0 = bp * 2, b1 = bp * 2 + 1;
    float acc0 = bias[j], acc1 = acc0;
    const float4* w4 = (const float4*)&w[(size_t)j * 512];
    #pragma unroll 8
    for (int q = 0; q < 128; q++) {
        float4 ww = w4[q];
        float4 x0 = ((const float4*)&s_in[b0][0])[q];
        float4 x1 = ((const float4*)&s_in[b1][0])[q];
        acc0 += ww.x * x0.x + ww.y * x0.y + ww.z * x0.z + ww.w * x0.w;
        acc1 += ww.x * x1.x + ww.y * x1.y + ww.z * x1.z + ww.w * x1.w;
    }
    out[(size_t)(bt * 8 + b0) * 512 + j] = fmaxf(acc0, 0.f);
    out[(size_t)(bt * 8 + b1) * 512 + j] = fmaxf(acc1, 0.f);
}

// ---------------------------------------------------------------------------
// Kernel 5: probs[b][s] = sum_h v_ptr[h]*tanh(ah[b][h][s] + out[b][h])
// tanh via (e^{2x}-1)/(e^{2x}+1) with __expf (accurate ~1e-6, MUFU-cheap)
// ---------------------------------------------------------------------------
__global__ __launch_bounds__(256) void probs_kernel(
    const float* __restrict__ ah, const float* __restrict__ v_ptr,
    float* __restrict__ probs)
{
    __shared__ float s_o[512];
    __shared__ float s_v[512];
    const int tid = threadIdx.x;
    const int b = blockIdx.y;
    const int s = blockIdx.x * 256 + tid;
    s_o[tid] = g_mlp_out[b][tid];
    s_o[tid + 256] = g_mlp_out[b][tid + 256];
    s_v[tid] = v_ptr[tid];
    s_v[tid + 256] = v_ptr[tid + 256];
    __syncthreads();
    const float* base = &ah[(size_t)b * HH * SS + s];
    float acc = 0.f;
    #pragma unroll 8
    for (int h = 0; h < 512; h++) {
        float x = base[(size_t)h * SS] + s_o[h];
        float e = __expf(2.0f * x);
        acc += s_v[h] * ((e - 1.0f) * __frcp_rn(e + 1.0f));
    }
    probs[b * SS + s] = acc;
}

// ---------------------------------------------------------------------------
extern "C" void kernel_launch(void* const* d_in, const int* in_sizes, int n_in,
                              void* d_out, int out_size)
{
    const float* ah    = (const float*)d_in[0];
    const float* v_att = (const float*)d_in[1];
    const float* W_att = (const float*)d_in[2];
    const float* v_ptr = (const float*)d_in[3];
    const float* fc1_w = (const float*)d_in[4];
    const float* fc1_b = (const float*)d_in[5];
    const float* fc2_w = (const float*)d_in[6];
    const float* fc2_b = (const float*)d_in[7];
    float* probs = (float*)d_out;

    scores_u_kernel<<<dim3(SS / 128, HH / 128, BB), 256>>>(ah, W_att, v_att);
    softmax_kernel<<<BB, 256>>>();
    context_kernel<<<(BB * HH) / 8, 256>>>(ah);
    linear_relu_kernel<<<dim3(8, 16), 256>>>(0, fc1_w, fc1_b);
    linear_relu_kernel<<<dim3(8, 16), 256>>>(1, fc2_w, fc2_b);
    probs_kernel<<<dim3(SS / 256, BB), 256>>>(ah, v_ptr, probs);
}

// round 5
// speedup vs baseline: 1.5074x; 1.5074x over previous
#include <cuda_runtime.h>
#include <cuda_fp16.h>
#include <math.h>
#include <stdint.h>

#define BB 128
#define HH 512
#define SS 2048

// Scratch (device globals: no allocations allowed)
__device__ __half g_Wh[HH * HH];        // fp16 copy of W_att
__device__ float g_u[BB][SS];
__device__ float g_attn[BB][SS];
__device__ float g_context[BB][HH];
__device__ float g_h1[BB][HH];
__device__ float g_mlp_out[BB][HH];

__device__ __forceinline__ uint32_t smem_u32(const void* p) {
    uint32_t a;
    asm("{ .reg .u64 t; cvta.to.shared.u64 t, %1; cvt.u32.u64 %0, t; }" : "=r"(a) : "l"(p));
    return a;
}
__device__ __forceinline__ float tanh_fast(float x) {
    float y; asm("tanh.approx.f32 %0, %1;" : "=f"(y) : "f"(x)); return y;
}
__device__ __forceinline__ unsigned f2h2(float a, float b) {
    __half2 h = __floats2half2_rn(a, b);
    return *reinterpret_cast<unsigned*>(&h);
}

#define LDSM_X4(r0, r1, r2, r3, addr) \
    asm volatile("ldmatrix.sync.aligned.m8n8.x4.shared.b16 {%0,%1,%2,%3}, [%4];" \
        : "=r"(r0), "=r"(r1), "=r"(r2), "=r"(r3) : "r"(addr))
#define LDSM_X4_T(r0, r1, r2, r3, addr) \
    asm volatile("ldmatrix.sync.aligned.m8n8.x4.trans.shared.b16 {%0,%1,%2,%3}, [%4];" \
        : "=r"(r0), "=r"(r1), "=r"(r2), "=r"(r3) : "r"(addr))
#define MMA16816(c, a, b) \
    asm volatile("mma.sync.aligned.m16n8k16.row.col.f32.f16.f16.f32 " \
        "{%0,%1,%2,%3}, {%4,%5,%6,%7}, {%8,%9}, {%0,%1,%2,%3};" \
        : "+f"((c)[0]), "+f"((c)[1]), "+f"((c)[2]), "+f"((c)[3]) \
        : "r"((a)[0]), "r"((a)[1]), "r"((a)[2]), "r"((a)[3]), \
          "r"((b)[0]), "r"((b)[1]))
#define CP16(dst, src) \
    asm volatile("cp.async.cg.shared.global [%0], [%1], 16;" :: "r"(dst), "l"(src) : "memory")
#define CP_COMMIT() asm volatile("cp.async.commit_group;" ::: "memory")
#define CP_WAIT2()  asm volatile("cp.async.wait_group 2;" ::: "memory")

// ---------------------------------------------------------------------------
// Kernel 0: W fp32 -> fp16 (one-time per launch, 1 MB read)
// ---------------------------------------------------------------------------
__global__ __launch_bounds__(256) void wconv_kernel(const float* __restrict__ W) {
    int i = blockIdx.x * 256 + threadIdx.x;          // float4 index
    float4 v = ((const float4*)W)[i];
    ((uint2*)g_Wh)[i] = make_uint2(f2h2(v.x, v.y), f2h2(v.z, v.w));
}

// ---------------------------------------------------------------------------
// Kernel 1: scores + u.  CTA = (s-tile 128, b).  B panel (512k x 128s fp16)
// resident in smem; staged during h-pass 0. A (W fp16) via cp.async 4-ring.
// u[b][s] = sum_h v_att[h]*tanh(score[h][s]) accumulated across 4 h-passes.
// ---------------------------------------------------------------------------
#define ASTRIDE 80
#define BSTRIDE 272
#define ABUF (128 * ASTRIDE)             // 10240 per ring slot
#define B_PANEL (512 * BSTRIDE)          // 139264
#define A_OFF  B_PANEL                   // 139264
#define SU_OFF (A_OFF + 4 * ABUF)        // 180224
#define K1_SMEM (SU_OFF + 512)

__global__ __launch_bounds__(256, 1) void scores_u_kernel(
    const float* __restrict__ ah, const float* __restrict__ v_att)
{
    extern __shared__ char smem[];
    const uint32_t sb = smem_u32(smem);
    const uint32_t sBb = sb;
    const uint32_t sAb = sb + A_OFF;
    float* su = (float*)(smem + SU_OFF);

    const int tid = threadIdx.x;
    const int wid = tid >> 5;
    const int lane = tid & 31;
    const int g = lane >> 2;
    const int t = lane & 3;
    const int warp_m = wid & 1;
    const int warp_n = wid >> 1;
    const int s0 = blockIdx.x * 128;
    const int b = blockIdx.y;

    const float* ahb = ah + (size_t)b * ((size_t)HH * SS);

    const int lr = lane & 7, sel = lane >> 3;
    const uint32_t a_off = (uint32_t)((warp_m * 64 + (sel & 1) * 8 + lr) * ASTRIDE
                                      + (sel >> 1) * 16);
    const uint32_t b_off = (uint32_t)(((sel & 1) * 8 + lr) * BSTRIDE
                                      + (warp_n * 32 + (sel >> 1) * 8) * 2);

    if (tid < 128) su[tid] = 0.f;

    float ucol[8];
    #pragma unroll
    for (int i = 0; i < 8; i++) ucol[i] = 0.f;

    // Stage B chunk 0 (rows k=0..31) before first pass
    float4 pb[4];
    #pragma unroll
    for (int f = 0; f < 4; f++) {
        int idx = tid + f * 256; int kk = idx >> 5, q2 = idx & 31;
        pb[f] = *(const float4*)&ahb[(size_t)kk * SS + s0 + q2 * 4];
    }
    #pragma unroll
    for (int f = 0; f < 4; f++) {
        int idx = tid + f * 256; int kk = idx >> 5, q2 = idx & 31;
        *(uint2*)(smem + kk * BSTRIDE + q2 * 8) =
            make_uint2(f2h2(pb[f].x, pb[f].y), f2h2(pb[f].z, pb[f].w));
    }

    for (int ht = 0; ht < 4; ht++) {
        const int h0 = ht * 128;
        // A ring prologue: chunks 0..2 of this pass
        #pragma unroll
        for (int c = 0; c < 3; c++) {
            #pragma unroll
            for (int f = 0; f < 2; f++) {
                int idx = tid + f * 256; int r = idx >> 2, q = idx & 3;
                CP16(sAb + c * ABUF + r * ASTRIDE + q * 16,
                     (const void*)(g_Wh + (size_t)(h0 + r) * HH + c * 32 + q * 8));
            }
            CP_COMMIT();
        }

        float acc[4][4][4];
        #pragma unroll
        for (int i = 0; i < 4; i++)
            #pragma unroll
            for (int j = 0; j < 4; j++)
                #pragma unroll
                for (int k = 0; k < 4; k++) acc[i][j][k] = 0.f;

        for (int i = 0; i < 16; i++) {
            CP_WAIT2();
            __syncthreads();
            // LDG B(i+1) during compute (pass 0 only)
            if (ht == 0 && i + 1 < 16) {
                int k0 = (i + 1) * 32;
                #pragma unroll
                for (int f = 0; f < 4; f++) {
                    int idx = tid + f * 256; int kk = idx >> 5, q2 = idx & 31;
                    pb[f] = *(const float4*)&ahb[(size_t)(k0 + kk) * SS + s0 + q2 * 4];
                }
            }
            // Issue A(i+3)
            if (i + 3 < 16) {
                int c = i + 3;
                #pragma unroll
                for (int f = 0; f < 2; f++) {
                    int idx = tid + f * 256; int r = idx >> 2, q = idx & 3;
                    CP16(sAb + (c & 3) * ABUF + r * ASTRIDE + q * 16,
                         (const void*)(g_Wh + (size_t)(h0 + r) * HH + c * 32 + q * 8));
                }
            }
            CP_COMMIT();
            // Compute chunk i
            {
                const uint32_t abase = sAb + (i & 3) * ABUF + a_off;
                const uint32_t bbase = sBb + (uint32_t)(i * 32) * BSTRIDE + b_off;
                #pragma unroll
                for (int kk = 0; kk < 2; kk++) {
                    uint32_t afr[4][4];
                    #pragma unroll
                    for (int ma = 0; ma < 4; ma++)
                        LDSM_X4(afr[ma][0], afr[ma][1], afr[ma][2], afr[ma][3],
                                abase + kk * 32 + ma * (16 * ASTRIDE));
                    uint32_t bfr[4][2];
                    #pragma unroll
                    for (int nb = 0; nb < 2; nb++)
                        LDSM_X4_T(bfr[2 * nb][0], bfr[2 * nb][1],
                                  bfr[2 * nb + 1][0], bfr[2 * nb + 1][1],
                                  bbase + kk * (16 * BSTRIDE) + nb * 32);
                    #pragma unroll
                    for (int ma = 0; ma < 4; ma++)
                        #pragma unroll
                        for (int na = 0; na < 4; na++)
                            MMA16816(acc[ma][na], afr[ma], bfr[na]);
                }
            }
            // STS B(i+1) (pass 0 only)
            if (ht == 0 && i + 1 < 16) {
                char* dst = smem + (size_t)(i + 1) * 32 * BSTRIDE;
                #pragma unroll
                for (int f = 0; f < 4; f++) {
                    int idx = tid + f * 256; int kk = idx >> 5, q2 = idx & 31;
                    *(uint2*)(dst + kk * BSTRIDE + q2 * 8) =
                        make_uint2(f2h2(pb[f].x, pb[f].y), f2h2(pb[f].z, pb[f].w));
                }
            }
        }
        // Per-pass epilogue: fold tanh + v_att into ucol
        float vr[4][2];
        #pragma unroll
        for (int ma = 0; ma < 4; ma++) {
            int r = h0 + warp_m * 64 + ma * 16 + g;
            vr[ma][0] = __ldg(&v_att[r]);
            vr[ma][1] = __ldg(&v_att[r + 8]);
        }
        #pragma unroll
        for (int ma = 0; ma < 4; ma++)
            #pragma unroll
            for (int na = 0; na < 4; na++) {
                ucol[na * 2 + 0] += vr[ma][0] * tanh_fast(acc[ma][na][0])
                                  + vr[ma][1] * tanh_fast(acc[ma][na][2]);
                ucol[na * 2 + 1] += vr[ma][0] * tanh_fast(acc[ma][na][1])
                                  + vr[ma][1] * tanh_fast(acc[ma][na][3]);
            }
    }

    __syncthreads();
    #pragma unroll
    for (int na = 0; na < 4; na++) {
        atomicAdd(&su[warp_n * 32 + na * 8 + 2 * t + 0], ucol[na * 2 + 0]);
        atomicAdd(&su[warp_n * 32 + na * 8 + 2 * t + 1], ucol[na * 2 + 1]);
    }
    __syncthreads();
    if (tid < 128) g_u[b][s0 + tid] = su[tid];
}

// ---------------------------------------------------------------------------
// Kernel 2: softmax over s per batch
// ---------------------------------------------------------------------------
__global__ __launch_bounds__(256) void softmax_kernel() {
    const int b = blockIdx.x, tid = threadIdx.x;
    __shared__ float red[8];
    __shared__ float bcast;
    float v[8];
    #pragma unroll
    for (int i = 0; i < 8; i++) v[i] = g_u[b][tid + i * 256];
    float m = -INFINITY;
    #pragma unroll
    for (int i = 0; i < 8; i++) m = fmaxf(m, v[i]);
    #pragma unroll
    for (int o = 16; o; o >>= 1) m = fmaxf(m, __shfl_xor_sync(0xffffffffu, m, o));
    if ((tid & 31) == 0) red[tid >> 5] = m;
    __syncthreads();
    if (tid == 0) {
        float x = red[0];
        #pragma unroll
        for (int i = 1; i < 8; i++) x = fmaxf(x, red[i]);
        bcast = x;
    }
    __syncthreads();
    m = bcast;
    float sum = 0.f;
    #pragma unroll
    for (int i = 0; i < 8; i++) { v[i] = expf(v[i] - m); sum += v[i]; }
    #pragma unroll
    for (int o = 16; o; o >>= 1) sum += __shfl_xor_sync(0xffffffffu, sum, o);
    __syncthreads();
    if ((tid & 31) == 0) red[tid >> 5] = sum;
    __syncthreads();
    if (tid == 0) {
        float x = 0.f;
        #pragma unroll
        for (int i = 0; i < 8; i++) x += red[i];
        bcast = x;
    }
    __syncthreads();
    float inv = 1.f / bcast;
    #pragma unroll
    for (int i = 0; i < 8; i++) g_attn[b][tid + i * 256] = v[i] * inv;
}

// ---------------------------------------------------------------------------
// Kernel 3: context[b][h] = sum_s attn[b][s]*ah[b][h][s], warp per row
// ---------------------------------------------------------------------------
__global__ __launch_bounds__(256) void context_kernel(const float* __restrict__ ah) {
    int gw = blockIdx.x * 8 + (threadIdx.x >> 5);
    int lane = threadIdx.x & 31;
    int b = gw >> 9, h = gw & 511;
    const float4* a4 = reinterpret_cast<const float4*>(&ah[((size_t)b * HH + h) * SS]);
    const float4* t4 = reinterpret_cast<const float4*>(&g_attn[b][0]);
    float acc = 0.f;
    #pragma unroll
    for (int it = 0; it < 16; it++) {
        float4 x = a4[it * 32 + lane];
        float4 w = t4[it * 32 + lane];
        acc += x.x * w.x + x.y * w.y + x.z * w.z + x.w * w.w;
    }
    #pragma unroll
    for (int o = 16; o; o >>= 1) acc += __shfl_xor_sync(0xffffffffu, acc, o);
    if (lane == 0) g_context[b][h] = acc;
}

// ---------------------------------------------------------------------------
// Kernel 4: out[b][j] = relu(in[b] . w[j] + bias[j])
// grid (8 j-tiles of 64, 16 b-tiles of 8), 512 thr: thread=(j, k-slice of 64)
// W slice register-resident; MLP=16 -> one DRAM latency round.
// ---------------------------------------------------------------------------
__global__ __launch_bounds__(512) void linear_relu_kernel(
    int phase, const float* __restrict__ w, const float* __restrict__ bias)
{
    __shared__ float s_in[8][512];
    __shared__ float red[8][64];
    const int jt = blockIdx.x, bt = blockIdx.y;
    const int tid = threadIdx.x;
    const float* in = phase ? &g_h1[0][0] : &g_context[0][0];
    float* out      = phase ? &g_mlp_out[0][0] : &g_h1[0][0];
    for (int t = tid; t < 8 * 128; t += 512) {
        int bb = t >> 7, q = t & 127;
        ((float4*)&s_in[bb][0])[q] = ((const float4*)&in[(size_t)(bt * 8 + bb) * 512])[q];
    }
    const int j = jt * 64 + (tid & 63);
    const int ks = tid >> 6;           // 0..7, slice of 64 floats
    float4 wreg[16];
    const float4* wr = (const float4*)&w[(size_t)j * 512 + ks * 64];
    #pragma unroll
    for (int q = 0; q < 16; q++) wreg[q] = wr[q];
    float bj = (ks == 0) ? bias[j] : 0.f;
    __syncthreads();
    #pragma unroll
    for (int bb = 0; bb < 8; bb++) {
        const float4* x = (const float4*)&s_in[bb][ks * 64];
        float acc = 0.f;
        #pragma unroll
        for (int q = 0; q < 16; q++) {
            float4 xx = x[q];
            acc += wreg[q].x * xx.x + wreg[q].y * xx.y
                 + wreg[q].z * xx.z + wreg[q].w * xx.w;
        }
        red[ks][tid & 63] = acc;
        __syncthreads();
        if (ks == 0) {
            float s = bj;
            #pragma unroll
            for (int k = 0; k < 8; k++) s += red[k][tid & 63];
            out[(size_t)(bt * 8 + bb) * 512 + j] = fmaxf(s, 0.f);
        }
        __syncthreads();
    }
}

// ---------------------------------------------------------------------------
// Kernel 5: probs[b][s] = sum_h v_ptr[h]*tanh(ah[b][h][s] + out[b][h])
// ---------------------------------------------------------------------------
__global__ __launch_bounds__(256) void probs_kernel(
    const float* __restrict__ ah, const float* __restrict__ v_ptr,
    float* __restrict__ probs)
{
    __shared__ float s_o[512];
    __shared__ float s_v[512];
    const int tid = threadIdx.x;
    const int b = blockIdx.y;
    const int s = blockIdx.x * 256 + tid;
    s_o[tid] = g_mlp_out[b][tid];
    s_o[tid + 256] = g_mlp_out[b][tid + 256];
    s_v[tid] = v_ptr[tid];
    s_v[tid + 256] = v_ptr[tid + 256];
    __syncthreads();
    const float* base = &ah[(size_t)b * HH * SS + s];
    float acc = 0.f;
    #pragma unroll 8
    for (int h = 0; h < 512; h++) {
        acc += s_v[h] * tanh_fast(base[(size_t)h * SS] + s_o[h]);
    }
    probs[b * SS + s] = acc;
}

// ---------------------------------------------------------------------------
extern "C" void kernel_launch(void* const* d_in, const int* in_sizes, int n_in,
                              void* d_out, int out_size)
{
    const float* ah    = (const float*)d_in[0];
    const float* v_att = (const float*)d_in[1];
    const float* W_att = (const float*)d_in[2];
    const float* v_ptr = (const float*)d_in[3];
    const float* fc1_w = (const float*)d_in[4];
    const float* fc1_b = (const float*)d_in[5];
    const float* fc2_w = (const float*)d_in[6];
    const float* fc2_b = (const float*)d_in[7];
    float* probs = (float*)d_out;

    cudaFuncSetAttribute(scores_u_kernel,
                         cudaFuncAttributeMaxDynamicSharedMemorySize, K1_SMEM);

    wconv_kernel<<<HH * HH / 1024, 256>>>(W_att);
    scores_u_kernel<<<dim3(SS / 128, BB), 256, K1_SMEM>>>(ah, v_att);
    softmax_kernel<<<BB, 256>>>();
    context_kernel<<<(BB * HH) / 8, 256>>>(ah);
    linear_relu_kernel<<<dim3(8, 16), 512>>>(0, fc1_w, fc1_b);
    linear_relu_kernel<<<dim3(8, 16), 512>>>(1, fc2_w, fc2_b);
    probs_kernel<<<dim3(SS / 256, BB), 256>>>(ah, v_ptr, probs);
}

// round 6
// speedup vs baseline: 1.7820x; 1.1822x over previous
#include <cuda_runtime.h>
#include <cuda_fp16.h>
#include <math.h>
#include <stdint.h>

#define BB 128
#define HH 512
#define SS 2048

// Scratch (device globals: no allocations allowed)
__device__ __half g_Wh[HH * HH];        // fp16 copy of W_att
__device__ float g_u[BB][SS];
__device__ float g_attn[BB][SS];
__device__ float g_context[BB][HH];
__device__ float g_h1[BB][HH];
__device__ float g_mlp_out[BB][HH];

__device__ __forceinline__ uint32_t smem_u32(const void* p) {
    uint32_t a;
    asm("{ .reg .u64 t; cvta.to.shared.u64 t, %1; cvt.u32.u64 %0, t; }" : "=r"(a) : "l"(p));
    return a;
}
__device__ __forceinline__ float tanh_fast(float x) {
    float y; asm("tanh.approx.f32 %0, %1;" : "=f"(y) : "f"(x)); return y;
}
__device__ __forceinline__ unsigned f2h2(float a, float b) {
    __half2 h = __floats2half2_rn(a, b);
    return *reinterpret_cast<unsigned*>(&h);
}

#define LDSM_X4(r0, r1, r2, r3, addr) \
    asm volatile("ldmatrix.sync.aligned.m8n8.x4.shared.b16 {%0,%1,%2,%3}, [%4];" \
        : "=r"(r0), "=r"(r1), "=r"(r2), "=r"(r3) : "r"(addr))
#define LDSM_X4_T(r0, r1, r2, r3, addr) \
    asm volatile("ldmatrix.sync.aligned.m8n8.x4.trans.shared.b16 {%0,%1,%2,%3}, [%4];" \
        : "=r"(r0), "=r"(r1), "=r"(r2), "=r"(r3) : "r"(addr))
#define MMA16816(c, a, b) \
    asm volatile("mma.sync.aligned.m16n8k16.row.col.f32.f16.f16.f32 " \
        "{%0,%1,%2,%3}, {%4,%5,%6,%7}, {%8,%9}, {%0,%1,%2,%3};" \
        : "+f"((c)[0]), "+f"((c)[1]), "+f"((c)[2]), "+f"((c)[3]) \
        : "r"((a)[0]), "r"((a)[1]), "r"((a)[2]), "r"((a)[3]), \
          "r"((b)[0]), "r"((b)[1]))
#define CP16(dst, src) \
    asm volatile("cp.async.cg.shared.global [%0], [%1], 16;" :: "r"(dst), "l"(src) : "memory")
#define CP_COMMIT() asm volatile("cp.async.commit_group;" ::: "memory")
#define CP_WAIT1()  asm volatile("cp.async.wait_group 1;" ::: "memory")

// ---------------------------------------------------------------------------
// Kernel 0: W fp32 -> fp16
// ---------------------------------------------------------------------------
__global__ __launch_bounds__(256) void wconv_kernel(const float* __restrict__ W) {
    int i = blockIdx.x * 256 + threadIdx.x;
    float4 v = ((const float4*)W)[i];
    ((uint2*)g_Wh)[i] = make_uint2(f2h2(v.x, v.y), f2h2(v.z, v.w));
}

// ---------------------------------------------------------------------------
// Kernel 1: scores + u.  CTA = (s-tile 64, b), 2 CTAs/SM.
// B panel (512k x 64s fp16, 72KB) resident; staged during h-pass 0.
// A (W fp16) cp.async 3-slot ring. 4 h-passes of 128 rows, fp16 MMA.
// ---------------------------------------------------------------------------
#define STILE 64
#define ASTRIDE 80
#define BSTRIDE 144
#define ABUF (128 * ASTRIDE)             // 10240 per ring slot
#define B_PANEL (512 * BSTRIDE)          // 73728
#define A_OFF  B_PANEL
#define SU_OFF (A_OFF + 3 * ABUF)        // 104448
#define K1_SMEM (SU_OFF + 256)           // 104704

__global__ __launch_bounds__(256, 2) void scores_u_kernel(
    const float* __restrict__ ah, const float* __restrict__ v_att)
{
    extern __shared__ char smem[];
    const uint32_t sb = smem_u32(smem);
    const uint32_t sBb = sb;
    const uint32_t sAb = sb + A_OFF;
    float* su = (float*)(smem + SU_OFF);

    const int tid = threadIdx.x;
    const int wid = tid >> 5;
    const int lane = tid & 31;
    const int g = lane >> 2;
    const int t = lane & 3;
    const int warp_m = wid & 1;        // 2 warps over 128 rows (64 each)
    const int warp_n = wid >> 1;       // 4 warps over 64 cols (16 each)
    const int s0 = blockIdx.x * STILE;
    const int b = blockIdx.y;

    const float* ahb = ah + (size_t)b * ((size_t)HH * SS);

    const int lr = lane & 7, sel = lane >> 3;
    const uint32_t a_off = (uint32_t)((warp_m * 64 + (sel & 1) * 8 + lr) * ASTRIDE
                                      + (sel >> 1) * 16);
    const uint32_t b_off = (uint32_t)(((sel & 1) * 8 + lr) * BSTRIDE
                                      + (warp_n * 16 + (sel >> 1) * 8) * 2);

    if (tid < 64) su[tid] = 0.f;

    float ucol[4];
    #pragma unroll
    for (int i = 0; i < 4; i++) ucol[i] = 0.f;

    // Stage B chunk 0 (k-rows 0..31)
    float4 pb[2];
    #pragma unroll
    for (int f = 0; f < 2; f++) {
        int idx = tid + f * 256; int kk = idx >> 4, q = idx & 15;
        pb[f] = *(const float4*)&ahb[(size_t)kk * SS + s0 + q * 4];
    }
    #pragma unroll
    for (int f = 0; f < 2; f++) {
        int idx = tid + f * 256; int kk = idx >> 4, q = idx & 15;
        *(uint2*)(smem + kk * BSTRIDE + q * 8) =
            make_uint2(f2h2(pb[f].x, pb[f].y), f2h2(pb[f].z, pb[f].w));
    }

    for (int ht = 0; ht < 4; ht++) {
        const int h0 = ht * 128;
        __syncthreads();   // protect ring slots from prev pass readers
        // Ring prologue: chunks 0,1
        #pragma unroll
        for (int c = 0; c < 2; c++) {
            #pragma unroll
            for (int f = 0; f < 2; f++) {
                int idx = tid + f * 256; int r = idx >> 2, q = idx & 3;
                CP16(sAb + c * ABUF + r * ASTRIDE + q * 16,
                     (const void*)(g_Wh + (size_t)(h0 + r) * HH + c * 32 + q * 8));
            }
            CP_COMMIT();
        }

        float acc[4][2][4];
        #pragma unroll
        for (int i = 0; i < 4; i++)
            #pragma unroll
            for (int j = 0; j < 2; j++)
                #pragma unroll
                for (int k = 0; k < 4; k++) acc[i][j][k] = 0.f;

        for (int i = 0; i < 16; i++) {
            CP_WAIT1();
            __syncthreads();
            // LDG B(i+1) during compute (pass 0 only)
            if (ht == 0 && i + 1 < 16) {
                int k0 = (i + 1) * 32;
                #pragma unroll
                for (int f = 0; f < 2; f++) {
                    int idx = tid + f * 256; int kk = idx >> 4, q = idx & 15;
                    pb[f] = *(const float4*)&ahb[(size_t)(k0 + kk) * SS + s0 + q * 4];
                }
            }
            // Issue A(i+2) into slot (i+2)%3 (freed slot (i-1)%3)
            if (i + 2 < 16) {
                int c = i + 2;
                uint32_t slotb = sAb + (c % 3) * ABUF;
                #pragma unroll
                for (int f = 0; f < 2; f++) {
                    int idx = tid + f * 256; int r = idx >> 2, q = idx & 3;
                    CP16(slotb + r * ASTRIDE + q * 16,
                         (const void*)(g_Wh + (size_t)(h0 + r) * HH + c * 32 + q * 8));
                }
            }
            CP_COMMIT();
            // Compute chunk i
            {
                const uint32_t abase = sAb + (i % 3) * ABUF + a_off;
                const uint32_t bbase = sBb + (uint32_t)(i * 32) * BSTRIDE + b_off;
                #pragma unroll
                for (int kk = 0; kk < 2; kk++) {
                    uint32_t afr[4][4];
                    #pragma unroll
                    for (int ma = 0; ma < 4; ma++)
                        LDSM_X4(afr[ma][0], afr[ma][1], afr[ma][2], afr[ma][3],
                                abase + kk * 32 + ma * (16 * ASTRIDE));
                    uint32_t bfr[2][2];
                    LDSM_X4_T(bfr[0][0], bfr[0][1], bfr[1][0], bfr[1][1],
                              bbase + kk * (16 * BSTRIDE));
                    #pragma unroll
                    for (int ma = 0; ma < 4; ma++)
                        #pragma unroll
                        for (int na = 0; na < 2; na++)
                            MMA16816(acc[ma][na], afr[ma], bfr[na]);
                }
            }
            // STS B(i+1) (pass 0 only)
            if (ht == 0 && i + 1 < 16) {
                char* dst = smem + (size_t)(i + 1) * 32 * BSTRIDE;
                #pragma unroll
                for (int f = 0; f < 2; f++) {
                    int idx = tid + f * 256; int kk = idx >> 4, q = idx & 15;
                    *(uint2*)(dst + kk * BSTRIDE + q * 8) =
                        make_uint2(f2h2(pb[f].x, pb[f].y), f2h2(pb[f].z, pb[f].w));
                }
            }
        }
        // Fold pass: tanh + v_att
        float vr[4][2];
        #pragma unroll
        for (int ma = 0; ma < 4; ma++) {
            int r = h0 + warp_m * 64 + ma * 16 + g;
            vr[ma][0] = __ldg(&v_att[r]);
            vr[ma][1] = __ldg(&v_att[r + 8]);
        }
        #pragma unroll
        for (int ma = 0; ma < 4; ma++)
            #pragma unroll
            for (int na = 0; na < 2; na++) {
                ucol[na * 2 + 0] += vr[ma][0] * tanh_fast(acc[ma][na][0])
                                  + vr[ma][1] * tanh_fast(acc[ma][na][2]);
                ucol[na * 2 + 1] += vr[ma][0] * tanh_fast(acc[ma][na][1])
                                  + vr[ma][1] * tanh_fast(acc[ma][na][3]);
            }
    }

    __syncthreads();
    #pragma unroll
    for (int na = 0; na < 2; na++) {
        atomicAdd(&su[warp_n * 16 + na * 8 + 2 * t + 0], ucol[na * 2 + 0]);
        atomicAdd(&su[warp_n * 16 + na * 8 + 2 * t + 1], ucol[na * 2 + 1]);
    }
    __syncthreads();
    if (tid < 64) g_u[b][s0 + tid] = su[tid];
}

// ---------------------------------------------------------------------------
// Kernel 2: softmax over s per batch
// ---------------------------------------------------------------------------
__global__ __launch_bounds__(256) void softmax_kernel() {
    const int b = blockIdx.x, tid = threadIdx.x;
    __shared__ float red[8];
    __shared__ float bcast;
    float v[8];
    #pragma unroll
    for (int i = 0; i < 8; i++) v[i] = g_u[b][tid + i * 256];
    float m = -INFINITY;
    #pragma unroll
    for (int i = 0; i < 8; i++) m = fmaxf(m, v[i]);
    #pragma unroll
    for (int o = 16; o; o >>= 1) m = fmaxf(m, __shfl_xor_sync(0xffffffffu, m, o));
    if ((tid & 31) == 0) red[tid >> 5] = m;
    __syncthreads();
    if (tid == 0) {
        float x = red[0];
        #pragma unroll
        for (int i = 1; i < 8; i++) x = fmaxf(x, red[i]);
        bcast = x;
    }
    __syncthreads();
    m = bcast;
    float sum = 0.f;
    #pragma unroll
    for (int i = 0; i < 8; i++) { v[i] = expf(v[i] - m); sum += v[i]; }
    #pragma unroll
    for (int o = 16; o; o >>= 1) sum += __shfl_xor_sync(0xffffffffu, sum, o);
    __syncthreads();
    if ((tid & 31) == 0) red[tid >> 5] = sum;
    __syncthreads();
    if (tid == 0) {
        float x = 0.f;
        #pragma unroll
        for (int i = 0; i < 8; i++) x += red[i];
        bcast = x;
    }
    __syncthreads();
    float inv = 1.f / bcast;
    #pragma unroll
    for (int i = 0; i < 8; i++) g_attn[b][tid + i * 256] = v[i] * inv;
}

// ---------------------------------------------------------------------------
// Kernel 3: context[b][h] = sum_s attn[b][s]*ah[b][h][s], warp per row
// ---------------------------------------------------------------------------
__global__ __launch_bounds__(256) void context_kernel(const float* __restrict__ ah) {
    int gw = blockIdx.x * 8 + (threadIdx.x >> 5);
    int lane = threadIdx.x & 31;
    int b = gw >> 9, h = gw & 511;
    const float4* a4 = reinterpret_cast<const float4*>(&ah[((size_t)b * HH + h) * SS]);
    const float4* t4 = reinterpret_cast<const float4*>(&g_attn[b][0]);
    float acc = 0.f;
    #pragma unroll
    for (int it = 0; it < 16; it++) {
        float4 x = a4[it * 32 + lane];
        float4 w = t4[it * 32 + lane];
        acc += x.x * w.x + x.y * w.y + x.z * w.z + x.w * w.w;
    }
    #pragma unroll
    for (int o = 16; o; o >>= 1) acc += __shfl_xor_sync(0xffffffffu, acc, o);
    if (lane == 0) g_context[b][h] = acc;
}

// ---------------------------------------------------------------------------
// Kernel 4: out[b][j] = relu(in[b] . w[j] + bias[j])
// ---------------------------------------------------------------------------
__global__ __launch_bounds__(512) void linear_relu_kernel(
    int phase, const float* __restrict__ w, const float* __restrict__ bias)
{
    __shared__ float s_in[8][512];
    __shared__ float red[8][64];
    const int jt = blockIdx.x, bt = blockIdx.y;
    const int tid = threadIdx.x;
    const float* in = phase ? &g_h1[0][0] : &g_context[0][0];
    float* out      = phase ? &g_mlp_out[0][0] : &g_h1[0][0];
    for (int t = tid; t < 8 * 128; t += 512) {
        int bb = t >> 7, q = t & 127;
        ((float4*)&s_in[bb][0])[q] = ((const float4*)&in[(size_t)(bt * 8 + bb) * 512])[q];
    }
    const int j = jt * 64 + (tid & 63);
    const int ks = tid >> 6;
    float4 wreg[16];
    const float4* wr = (const float4*)&w[(size_t)j * 512 + ks * 64];
    #pragma unroll
    for (int q = 0; q < 16; q++) wreg[q] = wr[q];
    float bj = (ks == 0) ? bias[j] : 0.f;
    __syncthreads();
    #pragma unroll
    for (int bb = 0; bb < 8; bb++) {
        const float4* x = (const float4*)&s_in[bb][ks * 64];
        float acc = 0.f;
        #pragma unroll
        for (int q = 0; q < 16; q++) {
            float4 xx = x[q];
            acc += wreg[q].x * xx.x + wreg[q].y * xx.y
                 + wreg[q].z * xx.z + wreg[q].w * xx.w;
        }
        red[ks][tid & 63] = acc;
        __syncthreads();
        if (ks == 0) {
            float s = bj;
            #pragma unroll
            for (int k = 0; k < 8; k++) s += red[k][tid & 63];
            out[(size_t)(bt * 8 + bb) * 512 + j] = fmaxf(s, 0.f);
        }
        __syncthreads();
    }
}

// ---------------------------------------------------------------------------
// Kernel 5: probs[b][s] = sum_h v_ptr[h]*tanh(ah[b][h][s] + out[b][h])
// ---------------------------------------------------------------------------
__global__ __launch_bounds__(256) void probs_kernel(
    const float* __restrict__ ah, const float* __restrict__ v_ptr,
    float* __restrict__ probs)
{
    __shared__ float s_o[512];
    __shared__ float s_v[512];
    const int tid = threadIdx.x;
    const int b = blockIdx.y;
    const int s = blockIdx.x * 256 + tid;
    s_o[tid] = g_mlp_out[b][tid];
    s_o[tid + 256] = g_mlp_out[b][tid + 256];
    s_v[tid] = v_ptr[tid];
    s_v[tid + 256] = v_ptr[tid + 256];
    __syncthreads();
    const float* base = &ah[(size_t)b * HH * SS + s];
    float acc = 0.f;
    #pragma unroll 8
    for (int h = 0; h < 512; h++) {
        acc += s_v[h] * tanh_fast(base[(size_t)h * SS] + s_o[h]);
    }
    probs[b * SS + s] = acc;
}

// ---------------------------------------------------------------------------
extern "C" void kernel_launch(void* const* d_in, const int* in_sizes, int n_in,
                              void* d_out, int out_size)
{
    const float* ah    = (const float*)d_in[0];
    const float* v_att = (const float*)d_in[1];
    const float* W_att = (const float*)d_in[2];
    const float* v_ptr = (const float*)d_in[3];
    const float* fc1_w = (const float*)d_in[4];
    const float* fc1_b = (const float*)d_in[5];
    const float* fc2_w = (const float*)d_in[6];
    const float* fc2_b = (const float*)d_in[7];
    float* probs = (float*)d_out;

    cudaFuncSetAttribute(scores_u_kernel,
                         cudaFuncAttributeMaxDynamicSharedMemorySize, K1_SMEM);

    wconv_kernel<<<HH * HH / 1024, 256>>>(W_att);
    scores_u_kernel<<<dim3(SS / STILE, BB), 256, K1_SMEM>>>(ah, v_att);
    softmax_kernel<<<BB, 256>>>();
    context_kernel<<<(BB * HH) / 8, 256>>>(ah);
    linear_relu_kernel<<<dim3(8, 16), 512>>>(0, fc1_w, fc1_b);
    linear_relu_kernel<<<dim3(8, 16), 512>>>(1, fc2_w, fc2_b);
    probs_kernel<<<dim3(SS / 256, BB), 256>>>(ah, v_ptr, probs);
}

// round 7
// speedup vs baseline: 1.8277x; 1.0256x over previous
#include <cuda_runtime.h>
#include <cuda_fp16.h>
#include <math.h>
#include <stdint.h>

#define BB 128
#define HH 512
#define SS 2048

// Scratch (device globals: no allocations allowed)
__device__ __half g_Wh[HH * HH];                 // fp16 W_att
__device__ __half g_ah_h[(size_t)BB * HH * SS];  // fp16 copy of all_hidden (256 MB)
__device__ float g_u[BB][SS];
__device__ float g_attn[BB][SS];
__device__ float g_context[BB][HH];
__device__ float g_h1[BB][HH];
__device__ float g_mlp_out[BB][HH];

__device__ __forceinline__ uint32_t smem_u32(const void* p) {
    uint32_t a;
    asm("{ .reg .u64 t; cvta.to.shared.u64 t, %1; cvt.u32.u64 %0, t; }" : "=r"(a) : "l"(p));
    return a;
}
__device__ __forceinline__ float tanh_fast(float x) {
    float y; asm("tanh.approx.f32 %0, %1;" : "=f"(y) : "f"(x)); return y;
}
__device__ __forceinline__ unsigned f2h2(float a, float b) {
    __half2 h = __floats2half2_rn(a, b);
    return *reinterpret_cast<unsigned*>(&h);
}

#define LDSM_X4(r0, r1, r2, r3, addr) \
    asm volatile("ldmatrix.sync.aligned.m8n8.x4.shared.b16 {%0,%1,%2,%3}, [%4];" \
        : "=r"(r0), "=r"(r1), "=r"(r2), "=r"(r3) : "r"(addr))
#define LDSM_X4_T(r0, r1, r2, r3, addr) \
    asm volatile("ldmatrix.sync.aligned.m8n8.x4.trans.shared.b16 {%0,%1,%2,%3}, [%4];" \
        : "=r"(r0), "=r"(r1), "=r"(r2), "=r"(r3) : "r"(addr))
#define MMA16816(c, a, b) \
    asm volatile("mma.sync.aligned.m16n8k16.row.col.f32.f16.f16.f32 " \
        "{%0,%1,%2,%3}, {%4,%5,%6,%7}, {%8,%9}, {%0,%1,%2,%3};" \
        : "+f"((c)[0]), "+f"((c)[1]), "+f"((c)[2]), "+f"((c)[3]) \
        : "r"((a)[0]), "r"((a)[1]), "r"((a)[2]), "r"((a)[3]), \
          "r"((b)[0]), "r"((b)[1]))
#define CP16(dst, src) \
    asm volatile("cp.async.cg.shared.global [%0], [%1], 16;" :: "r"(dst), "l"(src) : "memory")
#define CP_COMMIT() asm volatile("cp.async.commit_group;" ::: "memory")
#define CP_WAIT1()  asm volatile("cp.async.wait_group 1;" ::: "memory")

// ---------------------------------------------------------------------------
// Kernel 0: W fp32 -> fp16
// ---------------------------------------------------------------------------
__global__ __launch_bounds__(256) void wconv_kernel(const float* __restrict__ W) {
    int i = blockIdx.x * 256 + threadIdx.x;
    float4 v = ((const float4*)W)[i];
    ((uint2*)g_Wh)[i] = make_uint2(f2h2(v.x, v.y), f2h2(v.z, v.w));
}

// ---------------------------------------------------------------------------
// Kernel 1: scores + u.  CTA = (s-tile 64, b), 2 CTAs/SM.
// B panel (512k x 64s fp16, 72KB) resident; staged during h-pass 0 and ALSO
// streamed out to g_ah_h (fp16 copy consumed by context/probs kernels).
// A (W fp16) cp.async 3-slot ring. 4 h-passes of 128 rows, fp16 MMA.
// ---------------------------------------------------------------------------
#define STILE 64
#define ASTRIDE 80
#define BSTRIDE 144
#define ABUF (128 * ASTRIDE)             // 10240 per ring slot
#define B_PANEL (512 * BSTRIDE)          // 73728
#define A_OFF  B_PANEL
#define SU_OFF (A_OFF + 3 * ABUF)        // 104448
#define K1_SMEM (SU_OFF + 256)           // 104704

__global__ __launch_bounds__(256, 2) void scores_u_kernel(
    const float* __restrict__ ah, const float* __restrict__ v_att)
{
    extern __shared__ char smem[];
    const uint32_t sb = smem_u32(smem);
    const uint32_t sBb = sb;
    const uint32_t sAb = sb + A_OFF;
    float* su = (float*)(smem + SU_OFF);

    const int tid = threadIdx.x;
    const int wid = tid >> 5;
    const int lane = tid & 31;
    const int g = lane >> 2;
    const int t = lane & 3;
    const int warp_m = wid & 1;
    const int warp_n = wid >> 1;
    const int s0 = blockIdx.x * STILE;
    const int b = blockIdx.y;

    const float* ahb = ah + (size_t)b * ((size_t)HH * SS);
    __half* ahh = g_ah_h + (size_t)b * ((size_t)HH * SS);

    const int lr = lane & 7, sel = lane >> 3;
    const uint32_t a_off = (uint32_t)((warp_m * 64 + (sel & 1) * 8 + lr) * ASTRIDE
                                      + (sel >> 1) * 16);
    const uint32_t b_off = (uint32_t)(((sel & 1) * 8 + lr) * BSTRIDE
                                      + (warp_n * 16 + (sel >> 1) * 8) * 2);

    if (tid < 64) su[tid] = 0.f;

    float ucol[4];
    #pragma unroll
    for (int i = 0; i < 4; i++) ucol[i] = 0.f;

    // Stage B chunk 0 (k-rows 0..31): LDG fp32, cvt, STS + STG fp16 copy
    float4 pb[2];
    #pragma unroll
    for (int f = 0; f < 2; f++) {
        int idx = tid + f * 256; int kk = idx >> 4, q = idx & 15;
        pb[f] = *(const float4*)&ahb[(size_t)kk * SS + s0 + q * 4];
    }
    #pragma unroll
    for (int f = 0; f < 2; f++) {
        int idx = tid + f * 256; int kk = idx >> 4, q = idx & 15;
        uint2 hv = make_uint2(f2h2(pb[f].x, pb[f].y), f2h2(pb[f].z, pb[f].w));
        *(uint2*)(smem + kk * BSTRIDE + q * 8) = hv;
        *(uint2*)(ahh + (size_t)kk * SS + s0 + q * 4) = hv;
    }

    for (int ht = 0; ht < 4; ht++) {
        const int h0 = ht * 128;
        __syncthreads();
        #pragma unroll
        for (int c = 0; c < 2; c++) {
            #pragma unroll
            for (int f = 0; f < 2; f++) {
                int idx = tid + f * 256; int r = idx >> 2, q = idx & 3;
                CP16(sAb + c * ABUF + r * ASTRIDE + q * 16,
                     (const void*)(g_Wh + (size_t)(h0 + r) * HH + c * 32 + q * 8));
            }
            CP_COMMIT();
        }

        float acc[4][2][4];
        #pragma unroll
        for (int i = 0; i < 4; i++)
            #pragma unroll
            for (int j = 0; j < 2; j++)
                #pragma unroll
                for (int k = 0; k < 4; k++) acc[i][j][k] = 0.f;

        for (int i = 0; i < 16; i++) {
            CP_WAIT1();
            __syncthreads();
            if (ht == 0 && i + 1 < 16) {
                int k0 = (i + 1) * 32;
                #pragma unroll
                for (int f = 0; f < 2; f++) {
                    int idx = tid + f * 256; int kk = idx >> 4, q = idx & 15;
                    pb[f] = *(const float4*)&ahb[(size_t)(k0 + kk) * SS + s0 + q * 4];
                }
            }
            if (i + 2 < 16) {
                int c = i + 2;
                uint32_t slotb = sAb + (c % 3) * ABUF;
                #pragma unroll
                for (int f = 0; f < 2; f++) {
                    int idx = tid + f * 256; int r = idx >> 2, q = idx & 3;
                    CP16(slotb + r * ASTRIDE + q * 16,
                         (const void*)(g_Wh + (size_t)(h0 + r) * HH + c * 32 + q * 8));
                }
            }
            CP_COMMIT();
            // Compute chunk i
            {
                const uint32_t abase = sAb + (i % 3) * ABUF + a_off;
                const uint32_t bbase = sBb + (uint32_t)(i * 32) * BSTRIDE + b_off;
                #pragma unroll
                for (int kk = 0; kk < 2; kk++) {
                    uint32_t afr[4][4];
                    #pragma unroll
                    for (int ma = 0; ma < 4; ma++)
                        LDSM_X4(afr[ma][0], afr[ma][1], afr[ma][2], afr[ma][3],
                                abase + kk * 32 + ma * (16 * ASTRIDE));
                    uint32_t bfr[2][2];
                    LDSM_X4_T(bfr[0][0], bfr[0][1], bfr[1][0], bfr[1][1],
                              bbase + kk * (16 * BSTRIDE));
                    #pragma unroll
                    for (int ma = 0; ma < 4; ma++)
                        #pragma unroll
                        for (int na = 0; na < 2; na++)
                            MMA16816(acc[ma][na], afr[ma], bfr[na]);
                }
            }
            // STS + STG fp16 copy of B(i+1) (pass 0 only)
            if (ht == 0 && i + 1 < 16) {
                int k0 = (i + 1) * 32;
                char* dst = smem + (size_t)(i + 1) * 32 * BSTRIDE;
                #pragma unroll
                for (int f = 0; f < 2; f++) {
                    int idx = tid + f * 256; int kk = idx >> 4, q = idx & 15;
                    uint2 hv = make_uint2(f2h2(pb[f].x, pb[f].y), f2h2(pb[f].z, pb[f].w));
                    *(uint2*)(dst + kk * BSTRIDE + q * 8) = hv;
                    *(uint2*)(ahh + (size_t)(k0 + kk) * SS + s0 + q * 4) = hv;
                }
            }
        }
        // Fold pass: tanh + v_att
        float vr[4][2];
        #pragma unroll
        for (int ma = 0; ma < 4; ma++) {
            int r = h0 + warp_m * 64 + ma * 16 + g;
            vr[ma][0] = __ldg(&v_att[r]);
            vr[ma][1] = __ldg(&v_att[r + 8]);
        }
        #pragma unroll
        for (int ma = 0; ma < 4; ma++)
            #pragma unroll
            for (int na = 0; na < 2; na++) {
                ucol[na * 2 + 0] += vr[ma][0] * tanh_fast(acc[ma][na][0])
                                  + vr[ma][1] * tanh_fast(acc[ma][na][2]);
                ucol[na * 2 + 1] += vr[ma][0] * tanh_fast(acc[ma][na][1])
                                  + vr[ma][1] * tanh_fast(acc[ma][na][3]);
            }
    }

    __syncthreads();
    #pragma unroll
    for (int na = 0; na < 2; na++) {
        atomicAdd(&su[warp_n * 16 + na * 8 + 2 * t + 0], ucol[na * 2 + 0]);
        atomicAdd(&su[warp_n * 16 + na * 8 + 2 * t + 1], ucol[na * 2 + 1]);
    }
    __syncthreads();
    if (tid < 64) g_u[b][s0 + tid] = su[tid];
}

// ---------------------------------------------------------------------------
// Kernel 2: softmax over s per batch
// ---------------------------------------------------------------------------
__global__ __launch_bounds__(256) void softmax_kernel() {
    const int b = blockIdx.x, tid = threadIdx.x;
    __shared__ float red[8];
    __shared__ float bcast;
    float v[8];
    #pragma unroll
    for (int i = 0; i < 8; i++) v[i] = g_u[b][tid + i * 256];
    float m = -INFINITY;
    #pragma unroll
    for (int i = 0; i < 8; i++) m = fmaxf(m, v[i]);
    #pragma unroll
    for (int o = 16; o; o >>= 1) m = fmaxf(m, __shfl_xor_sync(0xffffffffu, m, o));
    if ((tid & 31) == 0) red[tid >> 5] = m;
    __syncthreads();
    if (tid == 0) {
        float x = red[0];
        #pragma unroll
        for (int i = 1; i < 8; i++) x = fmaxf(x, red[i]);
        bcast = x;
    }
    __syncthreads();
    m = bcast;
    float sum = 0.f;
    #pragma unroll
    for (int i = 0; i < 8; i++) { v[i] = expf(v[i] - m); sum += v[i]; }
    #pragma unroll
    for (int o = 16; o; o >>= 1) sum += __shfl_xor_sync(0xffffffffu, sum, o);
    __syncthreads();
    if ((tid & 31) == 0) red[tid >> 5] = sum;
    __syncthreads();
    if (tid == 0) {
        float x = 0.f;
        #pragma unroll
        for (int i = 0; i < 8; i++) x += red[i];
        bcast = x;
    }
    __syncthreads();
    float inv = 1.f / bcast;
    #pragma unroll
    for (int i = 0; i < 8; i++) g_attn[b][tid + i * 256] = v[i] * inv;
}

// ---------------------------------------------------------------------------
// Kernel 3: context[b][h] = sum_s attn[b][s]*ah_h[b][h][s]  (fp16 reads)
// ---------------------------------------------------------------------------
__global__ __launch_bounds__(256) void context_kernel() {
    int gw = blockIdx.x * 8 + (threadIdx.x >> 5);
    int lane = threadIdx.x & 31;
    int b = gw >> 9, h = gw & 511;
    const uint4* a8 = reinterpret_cast<const uint4*>(
        g_ah_h + ((size_t)b * HH + h) * SS);     // 8 halves per uint4
    const float4* t4 = reinterpret_cast<const float4*>(&g_attn[b][0]);
    float acc = 0.f;
    #pragma unroll
    for (int it = 0; it < 8; it++) {
        uint4 x = a8[it * 32 + lane];
        float4 w0 = t4[(it * 32 + lane) * 2];
        float4 w1 = t4[(it * 32 + lane) * 2 + 1];
        float2 f0 = __half22float2(*(__half2*)&x.x);
        float2 f1 = __half22float2(*(__half2*)&x.y);
        float2 f2 = __half22float2(*(__half2*)&x.z);
        float2 f3 = __half22float2(*(__half2*)&x.w);
        acc += f0.x * w0.x + f0.y * w0.y + f1.x * w0.z + f1.y * w0.w
             + f2.x * w1.x + f2.y * w1.y + f3.x * w1.z + f3.y * w1.w;
    }
    #pragma unroll
    for (int o = 16; o; o >>= 1) acc += __shfl_xor_sync(0xffffffffu, acc, o);
    if (lane == 0) g_context[b][h] = acc;
}

// ---------------------------------------------------------------------------
// Kernel 4: out[b][j] = relu(in[b] . w[j] + bias[j])
// ---------------------------------------------------------------------------
__global__ __launch_bounds__(512) void linear_relu_kernel(
    int phase, const float* __restrict__ w, const float* __restrict__ bias)
{
    __shared__ float s_in[8][512];
    __shared__ float red[8][64];
    const int jt = blockIdx.x, bt = blockIdx.y;
    const int tid = threadIdx.x;
    const float* in = phase ? &g_h1[0][0] : &g_context[0][0];
    float* out      = phase ? &g_mlp_out[0][0] : &g_h1[0][0];
    for (int t = tid; t < 8 * 128; t += 512) {
        int bb = t >> 7, q = t & 127;
        ((float4*)&s_in[bb][0])[q] = ((const float4*)&in[(size_t)(bt * 8 + bb) * 512])[q];
    }
    const int j = jt * 64 + (tid & 63);
    const int ks = tid >> 6;
    float4 wreg[16];
    const float4* wr = (const float4*)&w[(size_t)j * 512 + ks * 64];
    #pragma unroll
    for (int q = 0; q < 16; q++) wreg[q] = wr[q];
    float bj = (ks == 0) ? bias[j] : 0.f;
    __syncthreads();
    #pragma unroll
    for (int bb = 0; bb < 8; bb++) {
        const float4* x = (const float4*)&s_in[bb][ks * 64];
        float acc = 0.f;
        #pragma unroll
        for (int q = 0; q < 16; q++) {
            float4 xx = x[q];
            acc += wreg[q].x * xx.x + wreg[q].y * xx.y
                 + wreg[q].z * xx.z + wreg[q].w * xx.w;
        }
        red[ks][tid & 63] = acc;
        __syncthreads();
        if (ks == 0) {
            float s = bj;
            #pragma unroll
            for (int k = 0; k < 8; k++) s += red[k][tid & 63];
            out[(size_t)(bt * 8 + bb) * 512 + j] = fmaxf(s, 0.f);
        }
        __syncthreads();
    }
}

// ---------------------------------------------------------------------------
// Kernel 5: probs[b][s] = sum_h v_ptr[h]*tanh(ah_h[b][h][s] + out[b][h])
// fp16 reads, 2 s per thread via half2.
// ---------------------------------------------------------------------------
__global__ __launch_bounds__(256) void probs_kernel(
    const float* __restrict__ v_ptr, float* __restrict__ probs)
{
    __shared__ float s_o[512];
    __shared__ float s_v[512];
    const int tid = threadIdx.x;
    const int b = blockIdx.y;
    const int s2 = blockIdx.x * 512 + tid * 2;
    s_o[tid] = g_mlp_out[b][tid];
    s_o[tid + 256] = g_mlp_out[b][tid + 256];
    s_v[tid] = v_ptr[tid];
    s_v[tid + 256] = v_ptr[tid + 256];
    __syncthreads();
    const __half* base = g_ah_h + (size_t)b * HH * SS + s2;
    float ax = 0.f, ay = 0.f;
    #pragma unroll 8
    for (int h = 0; h < 512; h++) {
        float2 f = __half22float2(*(const __half2*)(base + (size_t)h * SS));
        float o = s_o[h], v = s_v[h];
        ax += v * tanh_fast(f.x + o);
        ay += v * tanh_fast(f.y + o);
    }
    *(float2*)&probs[(size_t)b * SS + s2] = make_float2(ax, ay);
}

// ---------------------------------------------------------------------------
extern "C" void kernel_launch(void* const* d_in, const int* in_sizes, int n_in,
                              void* d_out, int out_size)
{
    const float* ah    = (const float*)d_in[0];
    const float* v_att = (const float*)d_in[1];
    const float* W_att = (const float*)d_in[2];
    const float* v_ptr = (const float*)d_in[3];
    const float* fc1_w = (const float*)d_in[4];
    const float* fc1_b = (const float*)d_in[5];
    const float* fc2_w = (const float*)d_in[6];
    const float* fc2_b = (const float*)d_in[7];
    float* probs = (float*)d_out;

    cudaFuncSetAttribute(scores_u_kernel,
                         cudaFuncAttributeMaxDynamicSharedMemorySize, K1_SMEM);

    wconv_kernel<<<HH * HH / 1024, 256>>>(W_att);
    scores_u_kernel<<<dim3(SS / STILE, BB), 256, K1_SMEM>>>(ah, v_att);
    softmax_kernel<<<BB, 256>>>();
    context_kernel<<<(BB * HH) / 8, 256>>>();
    linear_relu_kernel<<<dim3(8, 16), 512>>>(0, fc1_w, fc1_b);
    linear_relu_kernel<<<dim3(8, 16), 512>>>(1, fc2_w, fc2_b);
    probs_kernel<<<dim3(SS / 512, BB), 256>>>(v_ptr, probs);
}